// round 6
// baseline (speedup 1.0000x reference)
#include <cuda_runtime.h>
#include <cuda_fp16.h>

// Problem constants
#define N_DRUG  10000
#define N_PROT  20000
#define DH      128
#define N_EDGES 1000000
#define N_LAB   500000

// ---------------- scratch (device globals) ----------------------------------
__device__ float g_tD[N_DRUG * DH];
__device__ float g_tP[N_PROT * DH];
__device__ float g_rD[N_DRUG * DH];
__device__ float g_rP[N_PROT * DH];
__device__ float g_hD[N_DRUG * DH];
__device__ float g_hP[N_PROT * DH];

__device__ int g_cntP[N_PROT];
__device__ int g_cntD[N_DRUG];
__device__ int g_offP[N_PROT + 1];
__device__ int g_offD[N_DRUG + 1];
__device__ int g_rnkP[N_EDGES];
__device__ int g_rnkD[N_EDGES];
__device__ int g_srcP[N_EDGES];
__device__ int g_srcD[N_EDGES];

// ---------------- small helpers ---------------------------------------------
__device__ __forceinline__ unsigned smem_u32(const void* p) {
    unsigned r;
    asm("{ .reg .u64 t; cvta.to.shared.u64 t, %1; cvt.u32.u64 %0, t; }"
        : "=r"(r) : "l"(p));
    return r;
}
__device__ __forceinline__ void ldsm_x4(unsigned* r, unsigned addr) {
    asm volatile("ldmatrix.sync.aligned.m8n8.x4.shared.b16 {%0,%1,%2,%3}, [%4];"
                 : "=r"(r[0]), "=r"(r[1]), "=r"(r[2]), "=r"(r[3]) : "r"(addr));
}
__device__ __forceinline__ void ldsm_x4_t(unsigned* r, unsigned addr) {
    asm volatile("ldmatrix.sync.aligned.m8n8.x4.trans.shared.b16 {%0,%1,%2,%3}, [%4];"
                 : "=r"(r[0]), "=r"(r[1]), "=r"(r[2]), "=r"(r[3]) : "r"(addr));
}
__device__ __forceinline__ void mma16816(float* d, const unsigned* a, const unsigned* b) {
    asm volatile("mma.sync.aligned.m16n8k16.row.col.f32.f16.f16.f32 "
                 "{%0,%1,%2,%3}, {%4,%5,%6,%7}, {%8,%9}, {%0,%1,%2,%3};"
                 : "+f"(d[0]), "+f"(d[1]), "+f"(d[2]), "+f"(d[3])
                 : "r"(a[0]), "r"(a[1]), "r"(a[2]), "r"(a[3]),
                   "r"(b[0]), "r"(b[1]));
}
// split fp32x4 into fp16 hi + fp16 residual
__device__ __forceinline__ void split_f4(float4 v, uint2& hi, uint2& lo) {
    __half2 h01 = __floats2half2_rn(v.x, v.y);
    __half2 h23 = __floats2half2_rn(v.z, v.w);
    float2 f01 = __half22float2(h01);
    float2 f23 = __half22float2(h23);
    __half2 l01 = __floats2half2_rn(v.x - f01.x, v.y - f01.y);
    __half2 l23 = __floats2half2_rn(v.z - f23.x, v.w - f23.y);
    hi.x = *(unsigned*)&h01; hi.y = *(unsigned*)&h23;
    lo.x = *(unsigned*)&l01; lo.y = *(unsigned*)&l23;
}

// ---------------- CSR build (per-type chains) ---------------------------------
__global__ void zero_kernel(int* __restrict__ p, int n) {
    int i = blockIdx.x * blockDim.x + threadIdx.x;
    if (i < n) p[i] = 0;
}

__global__ void hist_one(const int* __restrict__ keys, int* __restrict__ cnt,
                         int* __restrict__ rnk, int n) {
    int i = blockIdx.x * blockDim.x + threadIdx.x;
    if (i < n) rnk[i] = atomicAdd(&cnt[keys[i]], 1);
}

__global__ void scan_one(const int* __restrict__ cnt, int* __restrict__ off, int n) {
    __shared__ int sums[1024];
    int tid = threadIdx.x;
    int chunk = (n + 1023) >> 10;
    int start = tid * chunk;
    int end = start + chunk; if (end > n) end = n;
    if (start > n) start = n;

    int s = 0;
    for (int i = start; i < end; i++) s += cnt[i];
    sums[tid] = s;
    __syncthreads();
    for (int d = 1; d < 1024; d <<= 1) {
        int v = (tid >= d) ? sums[tid - d] : 0;
        __syncthreads();
        sums[tid] += v;
        __syncthreads();
    }
    int prefix = tid ? sums[tid - 1] : 0;
    for (int i = start; i < end; i++) {
        off[i] = prefix;
        prefix += cnt[i];
    }
    if (tid == 1023) off[n] = sums[1023];
}

__global__ void fill_one(const int* __restrict__ vals, const int* __restrict__ keys,
                         const int* __restrict__ off, const int* __restrict__ rnk,
                         int* __restrict__ dst, int n) {
    int i = blockIdx.x * blockDim.x + threadIdx.x;
    if (i < n) dst[off[keys[i]] + rnk[i]] = vals[i];
}

// ---------------- segment-sum: half-warp rows (16 lanes x 16B) ----------------
struct AggJob {
    const uint4* t;      // fp16 rows: 16 uint4 per row
    const float4* r;     // fp32 residual rows: 32 float4 per row
    const int* off;
    const int* src;
    float4* out;
    int n;
    int relu;
    int nblocks;
};

__device__ __forceinline__ void acc8_add(float* a, uint4 v) {
    float2 p0 = __half22float2(*(__half2*)&v.x);
    float2 p1 = __half22float2(*(__half2*)&v.y);
    float2 p2 = __half22float2(*(__half2*)&v.z);
    float2 p3 = __half22float2(*(__half2*)&v.w);
    a[0] += p0.x; a[1] += p0.y; a[2] += p1.x; a[3] += p1.y;
    a[4] += p2.x; a[5] += p2.y; a[6] += p3.x; a[7] += p3.y;
}

__global__ void __launch_bounds__(256) seg_agg2_kernel(AggJob ja, AggJob jb) {
    int b = blockIdx.x;
    bool first = (b < ja.nblocks);
    AggJob j = first ? ja : jb;
    int local = first ? b : b - ja.nblocks;
    int w = local * 8 + (threadIdx.x >> 5);
    int lane = threadIdx.x & 31;
    if (w >= j.n) return;

    int half_id = lane >> 4;
    int hl = lane & 15;
    int s = j.off[w], e = j.off[w + 1];

    float acc[8] = {0.f, 0.f, 0.f, 0.f, 0.f, 0.f, 0.f, 0.f};

    int i = s;
    for (; i + 4 <= e; i += 4) {
        int s0 = __ldg(j.src + i + half_id);
        int s1 = __ldg(j.src + i + 2 + half_id);
        uint4 v0 = __ldg(j.t + s0 * 16 + hl);
        uint4 v1 = __ldg(j.t + s1 * 16 + hl);
        acc8_add(acc, v0);
        acc8_add(acc, v1);
    }
    if (i + 2 <= e) {
        int s0 = __ldg(j.src + i + half_id);
        uint4 v0 = __ldg(j.t + s0 * 16 + hl);
        acc8_add(acc, v0);
        i += 2;
    }
    if (i < e) {
        int s0 = __ldg(j.src + i);
        uint4 v0 = __ldg(j.t + s0 * 16 + hl);
        if (half_id == 0) acc8_add(acc, v0);
    }

    // combine odd/even edge partial sums across half-warps
    #pragma unroll
    for (int q = 0; q < 8; q++)
        acc[q] += __shfl_xor_sync(0xffffffffu, acc[q], 16);

    if (half_id == 0) {
        float4 r0 = j.r[w * 32 + hl * 2];
        float4 r1 = j.r[w * 32 + hl * 2 + 1];
        float4 o0, o1;
        o0.x = acc[0] + r0.x; o0.y = acc[1] + r0.y;
        o0.z = acc[2] + r0.z; o0.w = acc[3] + r0.w;
        o1.x = acc[4] + r1.x; o1.y = acc[5] + r1.y;
        o1.z = acc[6] + r1.z; o1.w = acc[7] + r1.w;
        if (j.relu) {
            o0.x = fmaxf(o0.x, 0.f); o0.y = fmaxf(o0.y, 0.f);
            o0.z = fmaxf(o0.z, 0.f); o0.w = fmaxf(o0.w, 0.f);
            o1.x = fmaxf(o1.x, 0.f); o1.y = fmaxf(o1.y, 0.f);
            o1.z = fmaxf(o1.z, 0.f); o1.w = fmaxf(o1.w, 0.f);
        }
        j.out[w * 32 + hl * 2] = o0;
        j.out[w * 32 + hl * 2 + 1] = o1;
    }
}

// ---------------- 3-term split HMMA GEMM (fp32-accurate) ---------------------
// C = A[N,128]@B[128,128](+bias); A=Ah+Al, B=Bh+Bl in fp16;
// acc += Ah*Bh + Al*Bh + Ah*Bl  (Al*Bl ~ 2^-22, negligible)
#define BM 128
#define BN 128
#define BK 32
#define AS_H 40

struct GemmJob {
    const float* A;
    const float* B;
    const float* bias;
    void* C;
    int N;
    int c_half;
    int nblocks;
};
struct GemmJobs4 { GemmJob j[4]; int n; };

__global__ void __launch_bounds__(256, 2) gemm_multi_kernel(GemmJobs4 jobs) {
    __shared__ __align__(16) __half Ah[BM * AS_H];
    __shared__ __align__(16) __half Al[BM * AS_H];
    __shared__ __align__(16) __half Bh[BK * BN];
    __shared__ __align__(16) __half Bl[BK * BN];

    int b = blockIdx.x;
    int ji = 0, off = 0;
    while (ji < jobs.n - 1 && b >= off + jobs.j[ji].nblocks) {
        off += jobs.j[ji].nblocks;
        ji++;
    }
    GemmJob jb = jobs.j[ji];
    int m0 = (b - off) * BM;

    int tid = threadIdx.x;
    int lane = tid & 31;
    int wid = tid >> 5;
    int m0w = (wid & 3) * 32;
    int n0w = (wid >> 2) * 64;

    int a_row[4], a_c4[4], b_k[4], b_c4[4];
    #pragma unroll
    for (int l = 0; l < 4; l++) {
        int f = tid + l * 256;
        a_row[l] = f >> 3;
        a_c4[l] = f & 7;
        b_k[l] = f >> 5;
        b_c4[l] = f & 31;
    }

    float acc[2][8][4];
    #pragma unroll
    for (int mi = 0; mi < 2; mi++)
        #pragma unroll
        for (int ni = 0; ni < 8; ni++)
            #pragma unroll
            for (int q = 0; q < 4; q++) acc[mi][ni][q] = 0.f;

    #pragma unroll
    for (int t = 0; t < 4; t++) {
        if (t) __syncthreads();
        int kb = t * BK;

        #pragma unroll
        for (int l = 0; l < 4; l++) {
            int gr = m0 + a_row[l];
            float4 v = make_float4(0.f, 0.f, 0.f, 0.f);
            if (gr < jb.N) v = *(const float4*)(jb.A + gr * 128 + kb + a_c4[l] * 4);
            uint2 hi, lo;
            split_f4(v, hi, lo);
            int ao = a_row[l] * AS_H + a_c4[l] * 4;
            *(uint2*)&Ah[ao] = hi;
            *(uint2*)&Al[ao] = lo;

            float4 u = *(const float4*)(jb.B + (kb + b_k[l]) * 128 + b_c4[l] * 4);
            split_f4(u, hi, lo);
            int cc = (b_c4[l] >> 1) ^ (b_k[l] & 7);
            int bo = b_k[l] * BN + cc * 8 + (b_c4[l] & 1) * 4;
            *(uint2*)&Bh[bo] = hi;
            *(uint2*)&Bl[bo] = lo;
        }
        __syncthreads();

        #pragma unroll
        for (int ks = 0; ks < 2; ks++) {
            int k0 = ks * 16;
            unsigned ah[2][4], alr[2][4];
            #pragma unroll
            for (int mi = 0; mi < 2; mi++) {
                int ao = (m0w + mi * 16 + (lane & 15)) * AS_H + k0 +
                         ((lane >> 4) & 1) * 8;
                ldsm_x4(ah[mi], smem_u32(&Ah[ao]));
                ldsm_x4(alr[mi], smem_u32(&Al[ao]));
            }
            #pragma unroll
            for (int pi = 0; pi < 4; pi++) {
                int kr = k0 + (lane & 7) + ((lane >> 3) & 1) * 8;
                int nc = n0w + pi * 16 + (lane >> 4) * 8;
                int cc = (nc >> 3) ^ (kr & 7);
                unsigned bh[4], blr[4];
                ldsm_x4_t(bh, smem_u32(&Bh[kr * BN + cc * 8]));
                ldsm_x4_t(blr, smem_u32(&Bl[kr * BN + cc * 8]));
                #pragma unroll
                for (int mi = 0; mi < 2; mi++)
                    #pragma unroll
                    for (int sub = 0; sub < 2; sub++) {
                        int ni = pi * 2 + sub;
                        mma16816(acc[mi][ni], ah[mi], bh + 2 * sub);
                        mma16816(acc[mi][ni], alr[mi], bh + 2 * sub);
                        mma16816(acc[mi][ni], ah[mi], blr + 2 * sub);
                    }
            }
        }
    }

    // epilogue
    #pragma unroll
    for (int ni = 0; ni < 8; ni++) {
        int col = n0w + ni * 8 + (lane & 3) * 2;
        float bz0 = jb.bias ? __ldg(jb.bias + col) : 0.f;
        float bz1 = jb.bias ? __ldg(jb.bias + col + 1) : 0.f;
        #pragma unroll
        for (int mi = 0; mi < 2; mi++) {
            int r0 = m0 + m0w + mi * 16 + (lane >> 2);
            int r1 = r0 + 8;
            float e0 = acc[mi][ni][0] + bz0;
            float e1 = acc[mi][ni][1] + bz1;
            float e2 = acc[mi][ni][2] + bz0;
            float e3 = acc[mi][ni][3] + bz1;
            if (jb.c_half) {
                if (r0 < jb.N) {
                    __half2 h = __floats2half2_rn(e0, e1);
                    *(__half2*)((__half*)jb.C + r0 * 128 + col) = h;
                }
                if (r1 < jb.N) {
                    __half2 h = __floats2half2_rn(e2, e3);
                    *(__half2*)((__half*)jb.C + r1 * 128 + col) = h;
                }
            } else {
                if (r0 < jb.N)
                    *(float2*)((float*)jb.C + r0 * 128 + col) = make_float2(e0, e1);
                if (r1 < jb.N)
                    *(float2*)((float*)jb.C + r1 * 128 + col) = make_float2(e2, e3);
            }
        }
    }
}

// ---------------- decoder: half-warp dual-gather ------------------------------
__global__ void __launch_bounds__(256) decoder_kernel(
    const uint4* __restrict__ uD, const uint4* __restrict__ uP,
    const int* __restrict__ el_row, const int* __restrict__ el_col,
    const float4* __restrict__ bd1, const float4* __restrict__ w2v,
    const float* __restrict__ bd2, float* __restrict__ out, int L)
{
    int w = (blockIdx.x * blockDim.x + threadIdx.x) >> 5;
    int lane = threadIdx.x & 31;
    if (w >= L) return;
    int half_id = lane >> 4;
    int hl = lane & 15;

    int node = half_id ? __ldg(el_col + w) : __ldg(el_row + w);
    const uint4* base = half_id ? uP : uD;
    uint4 v = __ldg(base + node * 16 + hl);

    float f[8];
    *(float2*)&f[0] = __half22float2(*(__half2*)&v.x);
    *(float2*)&f[2] = __half22float2(*(__half2*)&v.y);
    *(float2*)&f[4] = __half22float2(*(__half2*)&v.z);
    *(float2*)&f[6] = __half22float2(*(__half2*)&v.w);

    float g[8];
    #pragma unroll
    for (int q = 0; q < 8; q++)
        g[q] = __shfl_xor_sync(0xffffffffu, f[q], 16);

    float p = 0.f;
    if (half_id == 0) {
        float4 b0 = __ldg(bd1 + hl * 2), b1 = __ldg(bd1 + hl * 2 + 1);
        float4 w0 = __ldg(w2v + hl * 2), w1 = __ldg(w2v + hl * 2 + 1);
        float bb[8] = {b0.x, b0.y, b0.z, b0.w, b1.x, b1.y, b1.z, b1.w};
        float ww[8] = {w0.x, w0.y, w0.z, w0.w, w1.x, w1.y, w1.z, w1.w};
        #pragma unroll
        for (int q = 0; q < 8; q++) {
            float h = fmaxf(f[q] + g[q] + bb[q], 0.f);
            p += h * ww[q];
        }
    }
    #pragma unroll
    for (int o = 8; o; o >>= 1) p += __shfl_down_sync(0xffffffffu, p, o);
    if (lane == 0) out[w] = p + __ldg(bd2);
}

// ---------------- launch ------------------------------------------------------
extern "C" void kernel_launch(void* const* d_in, const int* in_sizes, int n_in,
                              void* d_out, int out_size)
{
    const float* x_drug = (const float*)d_in[0];
    const float* x_prot = (const float*)d_in[1];
    const int*   ei_row = (const int*)d_in[2];
    const int*   ei_col = (const int*)d_in[3];
    const int*   el_row = (const int*)d_in[4];
    const int*   el_col = (const int*)d_in[5];
    const float* W1f_l = (const float*)d_in[6];
    const float* b1f   = (const float*)d_in[7];
    const float* W1f_r = (const float*)d_in[8];
    const float* W1r_l = (const float*)d_in[9];
    const float* b1r   = (const float*)d_in[10];
    const float* W1r_r = (const float*)d_in[11];
    const float* W2f_l = (const float*)d_in[12];
    const float* b2f   = (const float*)d_in[13];
    const float* W2f_r = (const float*)d_in[14];
    const float* W2r_l = (const float*)d_in[15];
    const float* b2r   = (const float*)d_in[16];
    const float* W2r_r = (const float*)d_in[17];
    const float* Wd1   = (const float*)d_in[18];
    const float* bd1   = (const float*)d_in[19];
    const float* Wd2   = (const float*)d_in[20];
    const float* bd2   = (const float*)d_in[21];

    const int nE = in_sizes[2];
    const int nL = in_sizes[4];

    float* outZd = (float*)d_out;
    float* outZp = outZd + (size_t)N_DRUG * DH;
    float* outO  = outZp + (size_t)N_PROT * DH;

    float *tD, *tP, *rD, *rP, *hD, *hP;
    cudaGetSymbolAddress((void**)&tD, g_tD);
    cudaGetSymbolAddress((void**)&tP, g_tP);
    cudaGetSymbolAddress((void**)&rD, g_rD);
    cudaGetSymbolAddress((void**)&rP, g_rP);
    cudaGetSymbolAddress((void**)&hD, g_hD);
    cudaGetSymbolAddress((void**)&hP, g_hP);
    int *cntP, *cntD, *offP, *offD, *rnkP, *rnkD, *srcP, *srcD;
    cudaGetSymbolAddress((void**)&cntP, g_cntP);
    cudaGetSymbolAddress((void**)&cntD, g_cntD);
    cudaGetSymbolAddress((void**)&offP, g_offP);
    cudaGetSymbolAddress((void**)&offD, g_offD);
    cudaGetSymbolAddress((void**)&rnkP, g_rnkP);
    cudaGetSymbolAddress((void**)&rnkD, g_rnkD);
    cudaGetSymbolAddress((void**)&srcP, g_srcP);
    cudaGetSymbolAddress((void**)&srcD, g_srcD);

    const int BD = (N_DRUG + BM - 1) / BM;   // 79
    const int BP = (N_PROT + BM - 1) / BM;   // 157
    const int gE = (nE + 255) / 256;

    // one-time host-side setup (first call = correctness run, not captured)
    static cudaStream_t sP = nullptr, sD = nullptr;
    static cudaEvent_t evFork = nullptr, evG1 = nullptr, evP = nullptr, evD = nullptr;
    if (!sP) {
        cudaStreamCreateWithFlags(&sP, cudaStreamNonBlocking);
        cudaStreamCreateWithFlags(&sD, cudaStreamNonBlocking);
        cudaEventCreateWithFlags(&evFork, cudaEventDisableTiming);
        cudaEventCreateWithFlags(&evG1, cudaEventDisableTiming);
        cudaEventCreateWithFlags(&evP, cudaEventDisableTiming);
        cudaEventCreateWithFlags(&evD, cudaEventDisableTiming);
    }

    // ---- fork two per-type CSR chains ----
    cudaEventRecord(evFork, 0);
    cudaStreamWaitEvent(sP, evFork, 0);
    cudaStreamWaitEvent(sD, evFork, 0);

    zero_kernel<<<(N_PROT + 255) / 256, 256, 0, sP>>>(cntP, N_PROT);
    hist_one<<<gE, 256, 0, sP>>>(ei_col, cntP, rnkP, nE);
    scan_one<<<1, 1024, 0, sP>>>(cntP, offP, N_PROT);
    fill_one<<<gE, 256, 0, sP>>>(ei_row, ei_col, offP, rnkP, srcP, nE);

    zero_kernel<<<(N_DRUG + 255) / 256, 256, 0, sD>>>(cntD, N_DRUG);
    hist_one<<<gE, 256, 0, sD>>>(ei_row, cntD, rnkD, nE);
    scan_one<<<1, 1024, 0, sD>>>(cntD, offD, N_DRUG);
    fill_one<<<gE, 256, 0, sD>>>(ei_col, ei_row, offD, rnkD, srcD, nE);

    // ---- layer 1 GEMMs (main stream, concurrent with CSR chains) ----
    {
        GemmJobs4 js;
        js.j[0] = { x_drug, W1f_l, nullptr, tD, N_DRUG, 1, BD };
        js.j[1] = { x_drug, W1r_r, b1r,     rD, N_DRUG, 0, BD };
        js.j[2] = { x_prot, W1r_l, nullptr, tP, N_PROT, 1, BP };
        js.j[3] = { x_prot, W1f_r, b1f,     rP, N_PROT, 0, BP };
        js.n = 4;
        gemm_multi_kernel<<<2 * (BD + BP), 256>>>(js);
    }
    cudaEventRecord(evG1, 0);

    // ---- layer 1 aggregations: each starts when its CSR + GEMM are done ----
    AggJob zeroJob = {};
    {
        cudaStreamWaitEvent(sP, evG1, 0);
        AggJob ja = { (const uint4*)tD, (const float4*)rP, offP, srcP,
                      (float4*)hP, N_PROT, 1, (N_PROT + 7) / 8 };
        seg_agg2_kernel<<<ja.nblocks, 256, 0, sP>>>(ja, zeroJob);
        cudaEventRecord(evP, sP);
    }
    {
        cudaStreamWaitEvent(sD, evG1, 0);
        AggJob ja = { (const uint4*)tP, (const float4*)rD, offD, srcD,
                      (float4*)hD, N_DRUG, 1, (N_DRUG + 7) / 8 };
        seg_agg2_kernel<<<ja.nblocks, 256, 0, sD>>>(ja, zeroJob);
        cudaEventRecord(evD, sD);
    }
    cudaStreamWaitEvent(0, evP, 0);
    cudaStreamWaitEvent(0, evD, 0);

    // ---- layer 2 GEMMs ----
    {
        GemmJobs4 js;
        js.j[0] = { hD, W2f_l, nullptr, tD, N_DRUG, 1, BD };
        js.j[1] = { hD, W2r_r, b2r,     rD, N_DRUG, 0, BD };
        js.j[2] = { hP, W2r_l, nullptr, tP, N_PROT, 1, BP };
        js.j[3] = { hP, W2f_r, b2f,     rP, N_PROT, 0, BP };
        js.n = 4;
        gemm_multi_kernel<<<2 * (BD + BP), 256>>>(js);
    }

    // ---- layer 2 aggregations (merged) ----
    {
        AggJob ja = { (const uint4*)tD, (const float4*)rP, offP, srcP,
                      (float4*)outZp, N_PROT, 0, (N_PROT + 7) / 8 };
        AggJob jb = { (const uint4*)tP, (const float4*)rD, offD, srcD,
                      (float4*)outZd, N_DRUG, 0, (N_DRUG + 7) / 8 };
        seg_agg2_kernel<<<ja.nblocks + jb.nblocks, 256>>>(ja, jb);
    }

    // ---- decoder node transforms ----
    {
        GemmJobs4 js;
        js.j[0] = { outZd, Wd1,             nullptr, tD, N_DRUG, 1, BD };
        js.j[1] = { outZp, Wd1 + 128 * 128, nullptr, tP, N_PROT, 1, BP };
        js.j[2] = js.j[0];
        js.j[3] = js.j[0];
        js.n = 2;
        gemm_multi_kernel<<<BD + BP, 256>>>(js);
    }

    // ---- decoder per-edge MLP ----
    decoder_kernel<<<(nL * 32 + 255) / 256, 256>>>(
        (const uint4*)tD, (const uint4*)tP, el_row, el_col,
        (const float4*)bd1, (const float4*)Wd2, bd2, outO, nL);
}